// round 1
// baseline (speedup 1.0000x reference)
#include <cuda_runtime.h>
#include <cstdint>

// ============================================================================
// PrimaryCapsuleLayer:
//   out[0 : B*512)          = interleave( x_scalar @ W_s + b_s , zeros )
//                             per row: 32 capsules x [8 gemm values | 8 zeros]
//   out[B*512 : B*512+B*384) = x_vector (straight copy)
// W_v / b_v are dead code in the reference (empty CG path) -> ignored.
// ============================================================================

#define KDIM 256   // SCALAR_FEAT
#define NDIM 256   // OUT_CAPS * half
#define BM 128
#define BN 64
#define BK 16
// 256 threads: 16 thread-rows (TM=8) x 16 thread-cols (TN=4)

__device__ __forceinline__ uint64_t pack2(float lo, float hi) {
    uint64_t r;
    asm("mov.b64 %0, {%1, %2};" : "=l"(r) : "f"(lo), "f"(hi));
    return r;
}

__device__ __forceinline__ void ffma2(uint64_t& d, uint64_t a, uint64_t b) {
    // packed fp32x2 FMA (Blackwell): d = a * b + d on both 32-bit halves
    asm("fma.rn.f32x2 %0, %1, %2, %0;" : "+l"(d) : "l"(a), "l"(b));
}

__device__ __forceinline__ float2 unpack2(uint64_t v) {
    float2 f;
    asm("mov.b64 {%0, %1}, %2;" : "=f"(f.x), "=f"(f.y) : "l"(v));
    return f;
}

__global__ __launch_bounds__(256) void caps_gemm_kernel(
    const float* __restrict__ X,      // [M, 256]
    const float* __restrict__ W,      // [256, 256] row-major (k, n)
    const float* __restrict__ bias,   // [256]
    float* __restrict__ out,          // [M, 512] capsule region
    int M)
{
    __shared__ __align__(16) float As[BK][BM];   // A transposed: As[k][m]
    __shared__ __align__(16) float Bs[BK][BN];   // Bs[k][n]

    const int tid  = threadIdx.x;
    const int trow = tid >> 4;    // 0..15 -> rows trow*8 .. +7
    const int tcol = tid & 15;    // 0..15 -> cols tcol*4 .. +3
    const int row0 = blockIdx.x * BM;
    const int col0 = blockIdx.y * BN;

    // 16 packed accumulators: 4 row-pairs x 4 cols
    uint64_t acc[4][4];
#pragma unroll
    for (int p = 0; p < 4; ++p)
#pragma unroll
        for (int j = 0; j < 4; ++j) acc[p][j] = 0ull;

    // loader coords
    const int a_row0 = (tid)       >> 2;  // iter 0: rows 0..63
    const int a_row1 = (tid + 256) >> 2;  // iter 1: rows 64..127
    const int a_q0   = tid & 3;           // which float4 along k
    const int b_k    = tid >> 4;          // 0..15
    const int b_nq   = tid & 15;          // float4 index along n

    for (int kt = 0; kt < KDIM; kt += BK) {
        // ---- load A tile [BM x BK], store transposed ----
        {
            float4 v0 = *reinterpret_cast<const float4*>(&X[(size_t)(row0 + a_row0) * KDIM + kt + a_q0 * 4]);
            float4 v1 = *reinterpret_cast<const float4*>(&X[(size_t)(row0 + a_row1) * KDIM + kt + a_q0 * 4]);
            As[a_q0 * 4 + 0][a_row0] = v0.x;
            As[a_q0 * 4 + 1][a_row0] = v0.y;
            As[a_q0 * 4 + 2][a_row0] = v0.z;
            As[a_q0 * 4 + 3][a_row0] = v0.w;
            As[a_q0 * 4 + 0][a_row1] = v1.x;
            As[a_q0 * 4 + 1][a_row1] = v1.y;
            As[a_q0 * 4 + 2][a_row1] = v1.z;
            As[a_q0 * 4 + 3][a_row1] = v1.w;
        }
        // ---- load B tile [BK x BN] ----
        {
            float4 v = *reinterpret_cast<const float4*>(&W[(size_t)(kt + b_k) * NDIM + col0 + b_nq * 4]);
            *reinterpret_cast<float4*>(&Bs[b_k][b_nq * 4]) = v;
        }
        __syncthreads();

#pragma unroll
        for (int k = 0; k < BK; ++k) {
            // A: 8 consecutive rows -> 4 packed row-pairs, direct 64-bit loads
            const uint64_t* arow = reinterpret_cast<const uint64_t*>(&As[k][trow * 8]);
            uint64_t a0 = arow[0], a1 = arow[1], a2 = arow[2], a3 = arow[3];
            // B: 4 columns, broadcast-packed
            float4 bvec = *reinterpret_cast<const float4*>(&Bs[k][tcol * 4]);
            uint64_t b0 = pack2(bvec.x, bvec.x);
            uint64_t b1 = pack2(bvec.y, bvec.y);
            uint64_t b2 = pack2(bvec.z, bvec.z);
            uint64_t b3 = pack2(bvec.w, bvec.w);

            ffma2(acc[0][0], a0, b0); ffma2(acc[0][1], a0, b1);
            ffma2(acc[0][2], a0, b2); ffma2(acc[0][3], a0, b3);
            ffma2(acc[1][0], a1, b0); ffma2(acc[1][1], a1, b1);
            ffma2(acc[1][2], a1, b2); ffma2(acc[1][3], a1, b3);
            ffma2(acc[2][0], a2, b0); ffma2(acc[2][1], a2, b1);
            ffma2(acc[2][2], a2, b2); ffma2(acc[2][3], a2, b3);
            ffma2(acc[3][0], a3, b0); ffma2(acc[3][1], a3, b1);
            ffma2(acc[3][2], a3, b2); ffma2(acc[3][3], a3, b3);
        }
        __syncthreads();
    }

    // ---- epilogue: bias add + interleaved store (8 gemm | 8 zero per capsule) ----
    const int n0  = col0 + tcol * 4;           // first of 4 consecutive output cols
    const int cap = n0 >> 3;                   // capsule index
    const int off = n0 & 7;                    // 0 or 4 within the scalar half
    const float4 bv = *reinterpret_cast<const float4*>(&bias[n0]);

#pragma unroll
    for (int p = 0; p < 4; ++p) {
        float2 c0 = unpack2(acc[p][0]);
        float2 c1 = unpack2(acc[p][1]);
        float2 c2 = unpack2(acc[p][2]);
        float2 c3 = unpack2(acc[p][3]);
        int r = row0 + trow * 8 + 2 * p;
        float4 lo = make_float4(c0.x + bv.x, c1.x + bv.y, c2.x + bv.z, c3.x + bv.w);
        float4 hi = make_float4(c0.y + bv.x, c1.y + bv.y, c2.y + bv.z, c3.y + bv.w);
        *reinterpret_cast<float4*>(&out[(size_t)r * 512 + cap * 16 + off])       = lo;
        *reinterpret_cast<float4*>(&out[(size_t)(r + 1) * 512 + cap * 16 + off]) = hi;
    }

    // zeros for the vector half of this capsule (one writer per capsule per thread-row)
    if ((tcol & 1) == 0) {
        const float4 z = make_float4(0.f, 0.f, 0.f, 0.f);
#pragma unroll
        for (int rr = 0; rr < 8; ++rr) {
            size_t base = (size_t)(row0 + trow * 8 + rr) * 512 + cap * 16 + 8;
            *reinterpret_cast<float4*>(&out[base])     = z;
            *reinterpret_cast<float4*>(&out[base + 4]) = z;
        }
    }
}

__global__ void vec_copy_kernel(const float4* __restrict__ src,
                                float4* __restrict__ dst, long n4)
{
    long i      = (long)blockIdx.x * blockDim.x + threadIdx.x;
    long stride = (long)gridDim.x * blockDim.x;
    for (; i < n4; i += stride) dst[i] = src[i];
}

extern "C" void kernel_launch(void* const* d_in, const int* in_sizes, int n_in,
                              void* d_out, int out_size)
{
    const float* x_scalar = (const float*)d_in[0];
    const float* x_vector = (const float*)d_in[1];
    const float* W_s      = (const float*)d_in[2];
    const float* b_s      = (const float*)d_in[3];
    // d_in[4] = W_v, d_in[5] = b_v : dead code in the reference
    float* out = (float*)d_out;

    const int M = in_sizes[0] / KDIM;   // batch

    dim3 grid(M / BM, NDIM / BN);       // 1024 x 4
    caps_gemm_kernel<<<grid, 256>>>(x_scalar, W_s, b_s, out, M);

    const long cap_elems = (long)M * 512;
    const long vec_elems = (long)out_size - cap_elems;
    if (vec_elems > 0) {
        long n4 = vec_elems / 4;
        vec_copy_kernel<<<2368, 256>>>((const float4*)x_vector,
                                       (float4*)(out + cap_elems), n4);
    }
}

// round 16
// speedup vs baseline: 1.8035x; 1.8035x over previous
#include <cuda_runtime.h>
#include <cuda_bf16.h>
#include <cstdint>

// ============================================================================
// PrimaryCapsuleLayer (sm_103-safe, no tcgen05 — harness compiles via
// compute_103 PTX which rejects all 'a'-suffix features):
//   out[0 : B*512)           = interleave( x_scalar @ W_s + b_s , zeros )
//   out[B*512 : B*512+B*384) = x_vector copy
// GEMM: 3-pass bf16 split (Xh@Wh + Xh@Wl + Xl@Wh) on mma.sync m16n8k16,
// fp32 accumulate. W pre-transposed/split by a prep kernel.
// ============================================================================

#define KDIM 256
#define NDIM 256
#define BM   128
#define BK   64
#define NCHUNK (KDIM / BK)   // 4
#define THREADS 512          // 16 warps: 4x4, warp tile 32m x 64n

// transposed bf16 weight halves, [n][k] K-major (filled by prep kernel)
__device__ __align__(16) __nv_bfloat16 g_Wth[NDIM * KDIM];
__device__ __align__(16) __nv_bfloat16 g_Wtl[NDIM * KDIM];

// ---- smem layout: 2 stages x (Ah 16K | Al 16K | Bh 32K | Bl 32K) = 192 KB
#define OFF_AH 0
#define OFF_AL 16384
#define OFF_BH 32768
#define OFF_BL 65536
#define STAGE  98304
#define SMEM_BYTES (2 * STAGE)

#define SW128(x) ((uint32_t)(x) ^ ((((uint32_t)(x)) >> 3) & 0x70))

// ---------------- helpers ----------------
__device__ __forceinline__ uint32_t smem_u32(const void* p) {
    uint32_t a;
    asm("{ .reg .u64 t; cvta.to.shared.u64 t, %1; cvt.u32.u64 %0, t; }" : "=r"(a) : "l"(p));
    return a;
}
__device__ __forceinline__ uint32_t pack_bf16x2(float lo, float hi) {
    uint32_t r;  // low half = bf16(lo), high half = bf16(hi)
    asm("cvt.rn.satfinite.bf16x2.f32 %0, %1, %2;" : "=r"(r) : "f"(hi), "f"(lo));
    return r;
}
__device__ __forceinline__ void cp_async16(uint32_t dst, const void* src) {
    asm volatile("cp.async.cg.shared.global [%0], [%1], 16;" :: "r"(dst), "l"(src) : "memory");
}
__device__ __forceinline__ void ldsm_x4(uint32_t* r, uint32_t addr) {
    asm volatile("ldmatrix.sync.aligned.m8n8.x4.shared.b16 {%0,%1,%2,%3}, [%4];"
                 : "=r"(r[0]), "=r"(r[1]), "=r"(r[2]), "=r"(r[3]) : "r"(addr));
}
__device__ __forceinline__ void mma_bf16(float* d, const uint32_t* a, const uint32_t* b) {
    asm volatile(
        "mma.sync.aligned.m16n8k16.row.col.f32.bf16.bf16.f32 "
        "{%0,%1,%2,%3}, {%4,%5,%6,%7}, {%8,%9}, {%0,%1,%2,%3};"
        : "+f"(d[0]), "+f"(d[1]), "+f"(d[2]), "+f"(d[3])
        : "r"(a[0]), "r"(a[1]), "r"(a[2]), "r"(a[3]), "r"(b[0]), "r"(b[1]));
}

// ---------------- prep: W [k][n] f32 -> Wt_h/Wt_l [n][k] bf16 ----------------
__global__ void prep_w_kernel(const float* __restrict__ W) {
    int tid = threadIdx.x;                       // 256
    int n   = blockIdx.x * 4 + (tid >> 6);
    int k0  = (tid & 63) * 4;
    float f[4];
#pragma unroll
    for (int j = 0; j < 4; ++j) f[j] = W[(size_t)(k0 + j) * NDIM + n];
    uint32_t h01 = pack_bf16x2(f[0], f[1]);
    uint32_t h23 = pack_bf16x2(f[2], f[3]);
    float l0 = f[0] - __uint_as_float(h01 << 16);
    float l1 = f[1] - __uint_as_float(h01 & 0xffff0000u);
    float l2 = f[2] - __uint_as_float(h23 << 16);
    float l3 = f[3] - __uint_as_float(h23 & 0xffff0000u);
    uint32_t L01 = pack_bf16x2(l0, l1);
    uint32_t L23 = pack_bf16x2(l2, l3);
    *reinterpret_cast<uint2*>(&g_Wth[n * KDIM + k0]) = make_uint2(h01, h23);
    *reinterpret_cast<uint2*>(&g_Wtl[n * KDIM + k0]) = make_uint2(L01, L23);
}

// ---------------- main GEMM ----------------
extern __shared__ char smem[];

__global__ void __launch_bounds__(THREADS) caps_gemm_mma(
    const float* __restrict__ X,
    const float* __restrict__ bias,
    float* __restrict__ out,
    int M)
{
    const uint32_t sb = smem_u32(smem);
    const int tid  = threadIdx.x;
    const int lane = tid & 31;
    const int wid  = tid >> 5;
    const int wm   = wid >> 2;       // 0..3 -> rows wm*32..+31
    const int wn   = wid & 3;        // 0..3 -> cols wn*64..+63
    const int row0 = blockIdx.x * BM;

    float acc[2][8][4];
#pragma unroll
    for (int mt = 0; mt < 2; ++mt)
#pragma unroll
        for (int nt = 0; nt < 8; ++nt)
#pragma unroll
            for (int j = 0; j < 4; ++j) acc[mt][nt][j] = 0.f;

    float4 aprf[4];

    // ---- prologue: B0 via cp.async, A0 via LDG+convert+STS ----
    {
        uint32_t dstb = sb;  // stage 0
#pragma unroll
        for (int i = 0; i < 4; ++i) {
            int idx = tid + i * THREADS;            // 0..2047
            int n = idx >> 3, u = idx & 7;
            uint32_t off = SW128(n * 128 + u * 16);
            cp_async16(dstb + OFF_BH + off, (const char*)g_Wth + n * 512 + u * 16);
            cp_async16(dstb + OFF_BL + off, (const char*)g_Wtl + n * 512 + u * 16);
        }
        asm volatile("cp.async.commit_group;" ::: "memory");
#pragma unroll
        for (int i = 0; i < 4; ++i) {
            int idx = tid + i * THREADS;
            int m = idx >> 4, q = idx & 15;
            aprf[i] = *reinterpret_cast<const float4*>(&X[(size_t)(row0 + m) * KDIM + q * 4]);
        }
#pragma unroll
        for (int i = 0; i < 4; ++i) {
            int idx = tid + i * THREADS;
            int m = idx >> 4, q = idx & 15;
            float4 v = aprf[i];
            uint32_t h01 = pack_bf16x2(v.x, v.y);
            uint32_t h23 = pack_bf16x2(v.z, v.w);
            float l0 = v.x - __uint_as_float(h01 << 16);
            float l1 = v.y - __uint_as_float(h01 & 0xffff0000u);
            float l2 = v.z - __uint_as_float(h23 << 16);
            float l3 = v.w - __uint_as_float(h23 & 0xffff0000u);
            uint32_t L01 = pack_bf16x2(l0, l1);
            uint32_t L23 = pack_bf16x2(l2, l3);
            uint32_t off = SW128(m * 128 + q * 8);
            *reinterpret_cast<uint2*>(smem + OFF_AH + off) = make_uint2(h01, h23);
            *reinterpret_cast<uint2*>(smem + OFF_AL + off) = make_uint2(L01, L23);
        }
        asm volatile("cp.async.wait_group 0;" ::: "memory");
        __syncthreads();
    }

    for (int c = 0; c < NCHUNK; ++c) {
        const int s = c & 1;

        // issue next chunk's loads (B -> smem via cp.async, A -> regs)
        if (c + 1 < NCHUNK) {
            uint32_t dstb = sb + (s ^ 1) * STAGE;
            int cb = (c + 1) * 128;                 // byte offset along K (bf16)
#pragma unroll
            for (int i = 0; i < 4; ++i) {
                int idx = tid + i * THREADS;
                int n = idx >> 3, u = idx & 7;
                uint32_t off = SW128(n * 128 + u * 16);
                cp_async16(dstb + OFF_BH + off, (const char*)g_Wth + n * 512 + cb + u * 16);
                cp_async16(dstb + OFF_BL + off, (const char*)g_Wtl + n * 512 + cb + u * 16);
            }
            asm volatile("cp.async.commit_group;" ::: "memory");
#pragma unroll
            for (int i = 0; i < 4; ++i) {
                int idx = tid + i * THREADS;
                int m = idx >> 4, q = idx & 15;
                aprf[i] = *reinterpret_cast<const float4*>(
                    &X[(size_t)(row0 + m) * KDIM + (c + 1) * BK + q * 4]);
            }
        }

        // ---- compute chunk c: 4 k-steps of 16 ----
        const uint32_t base = sb + s * STAGE;
#pragma unroll
        for (int ks = 0; ks < 4; ++ks) {
            const int arow  = wm * 32 + (lane & 15);
            const int acolb = ks * 32 + ((lane >> 4) << 4);
            const uint32_t aoff0 = SW128(arow * 128 + acolb);
            const uint32_t aoff1 = SW128((arow + 16) * 128 + acolb);

            uint32_t ah0[4], ah1[4];
            ldsm_x4(ah0, base + OFF_AH + aoff0);
            ldsm_x4(ah1, base + OFF_AH + aoff1);

            const int bnrow = wn * 64 + (lane & 7) + ((lane >> 4) << 3);
            const int bcolb = ks * 32 + (((lane >> 3) & 1) << 4);
            uint32_t bh[8][2];
#pragma unroll
            for (int g = 0; g < 4; ++g) {
                uint32_t r[4];
                ldsm_x4(r, base + OFF_BH + SW128((bnrow + g * 16) * 128 + bcolb));
                bh[2 * g][0] = r[0]; bh[2 * g][1] = r[1];
                bh[2 * g + 1][0] = r[2]; bh[2 * g + 1][1] = r[3];
            }
            // hh
#pragma unroll
            for (int nt = 0; nt < 8; ++nt) {
                mma_bf16(acc[0][nt], ah0, bh[nt]);
                mma_bf16(acc[1][nt], ah1, bh[nt]);
            }
            // lh (Al x Bh)
            {
                uint32_t al0[4], al1[4];
                ldsm_x4(al0, base + OFF_AL + aoff0);
                ldsm_x4(al1, base + OFF_AL + aoff1);
#pragma unroll
                for (int nt = 0; nt < 8; ++nt) {
                    mma_bf16(acc[0][nt], al0, bh[nt]);
                    mma_bf16(acc[1][nt], al1, bh[nt]);
                }
            }
            // hl (Ah x Bl)
            {
                uint32_t bl[8][2];
#pragma unroll
                for (int g = 0; g < 4; ++g) {
                    uint32_t r[4];
                    ldsm_x4(r, base + OFF_BL + SW128((bnrow + g * 16) * 128 + bcolb));
                    bl[2 * g][0] = r[0]; bl[2 * g][1] = r[1];
                    bl[2 * g + 1][0] = r[2]; bl[2 * g + 1][1] = r[3];
                }
#pragma unroll
                for (int nt = 0; nt < 8; ++nt) {
                    mma_bf16(acc[0][nt], ah0, bl[nt]);
                    mma_bf16(acc[1][nt], ah1, bl[nt]);
                }
            }
        }

        // ---- store next A chunk, drain next B ----
        if (c + 1 < NCHUNK) {
            char* stg = smem + (s ^ 1) * STAGE;
#pragma unroll
            for (int i = 0; i < 4; ++i) {
                int idx = tid + i * THREADS;
                int m = idx >> 4, q = idx & 15;
                float4 v = aprf[i];
                uint32_t h01 = pack_bf16x2(v.x, v.y);
                uint32_t h23 = pack_bf16x2(v.z, v.w);
                float l0 = v.x - __uint_as_float(h01 << 16);
                float l1 = v.y - __uint_as_float(h01 & 0xffff0000u);
                float l2 = v.z - __uint_as_float(h23 << 16);
                float l3 = v.w - __uint_as_float(h23 & 0xffff0000u);
                uint32_t L01 = pack_bf16x2(l0, l1);
                uint32_t L23 = pack_bf16x2(l2, l3);
                uint32_t off = SW128(m * 128 + q * 8);
                *reinterpret_cast<uint2*>(stg + OFF_AH + off) = make_uint2(h01, h23);
                *reinterpret_cast<uint2*>(stg + OFF_AL + off) = make_uint2(L01, L23);
            }
            asm volatile("cp.async.wait_group 0;" ::: "memory");
        }
        __syncthreads();
    }

    // ---- epilogue: bias + interleaved store [8 gemm | 8 zero] per capsule ----
    const int rb = row0 + wm * 32 + (lane >> 2);
    const int cw = (lane & 3) * 2;
    const float4 z = make_float4(0.f, 0.f, 0.f, 0.f);
#pragma unroll
    for (int mt = 0; mt < 2; ++mt) {
        const int r1 = rb + mt * 16;
#pragma unroll
        for (int nt = 0; nt < 8; ++nt) {
            const int n   = wn * 64 + nt * 8 + cw;
            const int cap = wn * 8 + nt;
            const float b0 = __ldg(&bias[n]);
            const float b1 = __ldg(&bias[n + 1]);
            float2 v1 = make_float2(acc[mt][nt][0] + b0, acc[mt][nt][1] + b1);
            float2 v2 = make_float2(acc[mt][nt][2] + b0, acc[mt][nt][3] + b1);
            size_t o1 = (size_t)r1 * 512 + cap * 16;
            size_t o2 = (size_t)(r1 + 8) * 512 + cap * 16;
            *reinterpret_cast<float2*>(&out[o1 + cw]) = v1;
            *reinterpret_cast<float2*>(&out[o2 + cw]) = v2;
            if ((lane & 3) == 0) {
                *reinterpret_cast<float4*>(&out[o1 + 8])  = z;
                *reinterpret_cast<float4*>(&out[o1 + 12]) = z;
                *reinterpret_cast<float4*>(&out[o2 + 8])  = z;
                *reinterpret_cast<float4*>(&out[o2 + 12]) = z;
            }
        }
    }
}

// ---------------- vector passthrough copy ----------------
__global__ void vec_copy_kernel(const float4* __restrict__ src,
                                float4* __restrict__ dst, long n4)
{
    long i      = (long)blockIdx.x * blockDim.x + threadIdx.x;
    long stride = (long)gridDim.x * blockDim.x;
    for (; i < n4; i += stride) dst[i] = src[i];
}

extern "C" void kernel_launch(void* const* d_in, const int* in_sizes, int n_in,
                              void* d_out, int out_size)
{
    const float* x_scalar = (const float*)d_in[0];
    const float* x_vector = (const float*)d_in[1];
    const float* W_s      = (const float*)d_in[2];
    const float* b_s      = (const float*)d_in[3];
    // d_in[4], d_in[5] (W_v, b_v): dead code in the reference
    float* out = (float*)d_out;

    const int M = in_sizes[0] / KDIM;

    static bool attr_set = false;
    if (!attr_set) {
        cudaFuncSetAttribute(caps_gemm_mma,
                             cudaFuncAttributeMaxDynamicSharedMemorySize, SMEM_BYTES);
        attr_set = true;
    }

    prep_w_kernel<<<NDIM / 4, 256>>>(W_s);
    caps_gemm_mma<<<M / BM, THREADS, SMEM_BYTES>>>(x_scalar, b_s, out, M);

    const long cap_elems = (long)M * 512;
    const long vec_elems = (long)out_size - cap_elems;
    if (vec_elems > 0) {
        vec_copy_kernel<<<2368, 256>>>((const float4*)x_vector,
                                       (float4*)(out + cap_elems), vec_elems / 4);
    }
}